// round 3
// baseline (speedup 1.0000x reference)
#include <cuda_runtime.h>
#include <math.h>

// Problem constants (fixed by setup_inputs): B=1024, L=1024, O=4096, 20 iters.
#define B_DIM 1024
#define L_DIM 1024
#define O_DIM 4096
#define N_ITERS 20

#define INF_LR    0.01f
#define SPARSE_Z  1e-3f

// Scratch (no cudaMalloc allowed): z ping-pong + intermediate G.
__device__ float g_Z0[B_DIM * L_DIM];
__device__ float g_Z1[B_DIM * L_DIM];
__device__ float g_G [B_DIM * O_DIM];

// ---------------------------------------------------------------------------
// Packed fp32x2 helpers (sm_100+ PTX; ptxas will not auto-fuse — must be PTX)
// ---------------------------------------------------------------------------
__device__ __forceinline__ unsigned long long pack_dup(float a) {
    unsigned long long r;
    asm("mov.b64 %0, {%1, %1};" : "=l"(r) : "f"(a));
    return r;
}
__device__ __forceinline__ void fma2(unsigned long long& c,
                                     unsigned long long a,
                                     unsigned long long b) {
    asm("fma.rn.f32x2 %0, %1, %2, %0;" : "+l"(c) : "l"(a), "l"(b));
}
__device__ __forceinline__ float2 unpack2(unsigned long long v) {
    float2 f;
    asm("mov.b64 {%0, %1}, %2;" : "=f"(f.x), "=f"(f.y) : "l"(v));
    return f;
}

// ---------------------------------------------------------------------------
// z0 = broadcast(mu) over batch
// ---------------------------------------------------------------------------
__global__ void init_z_kernel(const float* __restrict__ mu, float* __restrict__ z) {
    int i = blockIdx.x * blockDim.x + threadIdx.x;   // float4 index
    const float4* mu4 = (const float4*)mu;
    float4* z4 = (float4*)z;
    z4[i] = mu4[i & (L_DIM / 4 - 1)];
}

// ---------------------------------------------------------------------------
// Fused GEMM.
//   C[M,N] = A[M,K] * B
//   TRANSB=true : B is [N,K] row-major (C = A * B^T)   -- GEMM1, B = W[O,L]
//   TRANSB=false: B is [K,N] row-major (C = A * B)     -- GEMM2, B = W[O,L]
//   EPI=1: G = (1 - tanh(C)^2) * (X - tanh(C)),  X = x [M,N]
//   EPI=2: OUT = 0.99*Z + 0.01*mu + 0.01*C - 1e-5*sign(Z),  X = z_cur [M,N]
// ---------------------------------------------------------------------------
template <int BM, int BN, int BK, int TM, int TN, bool TRANSB, int EPI>
__global__ void __launch_bounds__((BM / TM) * (BN / TN))
gemm_fused(const float* __restrict__ A, const float* __restrict__ Bm,
           const float* __restrict__ X, const float* __restrict__ MU,
           float* __restrict__ OUT, int M, int N, int K) {
    constexpr int THREADS = (BM / TM) * (BN / TN);
    constexpr int AP = BM + 4;                    // padded pitch (16B-aligned rows)
    constexpr int BP = TRANSB ? (BN + 4) : BN;

    __shared__ float As[BK * AP];
    __shared__ float Bs[BK * BP];

    const int tid = threadIdx.x;
    const int tx = tid % (BN / TN);
    const int ty = tid / (BN / TN);
    const int bm = blockIdx.y * BM;
    const int bn = blockIdx.x * BN;

    unsigned long long acc[TM][TN / 2];
#pragma unroll
    for (int i = 0; i < TM; i++)
#pragma unroll
        for (int j = 0; j < TN / 2; j++) acc[i][j] = 0ull;

    for (int k0 = 0; k0 < K; k0 += BK) {
        // --- A tile: [BM, BK] from row-major [M,K], transposed into As[k][m]
#pragma unroll
        for (int t = 0; t < (BM * BK) / (4 * THREADS); ++t) {
            int idx = tid + t * THREADS;
            int row = idx / (BK / 4);
            int kc = (idx % (BK / 4)) * 4;
            float4 v = *(const float4*)&A[(size_t)(bm + row) * K + k0 + kc];
            As[(kc + 0) * AP + row] = v.x;
            As[(kc + 1) * AP + row] = v.y;
            As[(kc + 2) * AP + row] = v.z;
            As[(kc + 3) * AP + row] = v.w;
        }
        // --- B tile
        if (TRANSB) {
            // B is [N,K]: transpose into Bs[k][n]
#pragma unroll
            for (int t = 0; t < (BN * BK) / (4 * THREADS); ++t) {
                int idx = tid + t * THREADS;
                int row = idx / (BK / 4);
                int kc = (idx % (BK / 4)) * 4;
                float4 v = *(const float4*)&Bm[(size_t)(bn + row) * K + k0 + kc];
                Bs[(kc + 0) * BP + row] = v.x;
                Bs[(kc + 1) * BP + row] = v.y;
                Bs[(kc + 2) * BP + row] = v.z;
                Bs[(kc + 3) * BP + row] = v.w;
            }
        } else {
            // B is [K,N]: direct copy into Bs[k][n]
#pragma unroll
            for (int t = 0; t < (BK * BN) / (4 * THREADS); ++t) {
                int idx = tid + t * THREADS;
                int kr = idx / (BN / 4);
                int nc = (idx % (BN / 4)) * 4;
                *(float4*)&Bs[kr * BP + nc] =
                    *(const float4*)&Bm[(size_t)(k0 + kr) * N + bn + nc];
            }
        }
        __syncthreads();

#pragma unroll
        for (int k = 0; k < BK; ++k) {
            float a[TM];
#pragma unroll
            for (int i = 0; i < TM; i += 4)
                *(float4*)&a[i] = *(const float4*)&As[k * AP + ty * TM + i];
            unsigned long long b[TN / 2];
            {
                const unsigned long long* bs2 =
                    (const unsigned long long*)&Bs[k * BP + tx * TN];
#pragma unroll
                for (int j = 0; j < TN / 2; j++) b[j] = bs2[j];
            }
#pragma unroll
            for (int i = 0; i < TM; i++) {
                unsigned long long ad = pack_dup(a[i]);
#pragma unroll
                for (int j = 0; j < TN / 2; j++) fma2(acc[i][j], ad, b[j]);
            }
        }
        __syncthreads();
    }

    // --- fused epilogues ---
#pragma unroll
    for (int i = 0; i < TM; i++) {
        int r = bm + ty * TM + i;
#pragma unroll
        for (int j = 0; j < TN / 2; j++) {
            int c = bn + tx * TN + 2 * j;
            size_t off = (size_t)r * N + c;
            float2 v = unpack2(acc[i][j]);
            if (EPI == 1) {
                float2 xv = *(const float2*)&X[off];
                float p0 = tanhf(v.x);
                float p1 = tanhf(v.y);
                float2 o;
                o.x = (1.0f - p0 * p0) * (xv.x - p0);
                o.y = (1.0f - p1 * p1) * (xv.y - p1);
                *(float2*)&OUT[off] = o;
            } else {
                float2 zv = *(const float2*)&X[off];
                float2 mv = *(const float2*)&MU[c];
                float s0 = (float)((zv.x > 0.0f) - (zv.x < 0.0f));
                float s1 = (float)((zv.y > 0.0f) - (zv.y < 0.0f));
                float2 o;
                o.x = (1.0f - INF_LR) * zv.x + INF_LR * mv.x + INF_LR * v.x
                      - (INF_LR * SPARSE_Z) * s0;
                o.y = (1.0f - INF_LR) * zv.y + INF_LR * mv.y + INF_LR * v.y
                      - (INF_LR * SPARSE_Z) * s1;
                *(float2*)&OUT[off] = o;
            }
        }
    }
}

// ---------------------------------------------------------------------------
// Launch: init z, then 20x (fused GEMM1 -> fused GEMM2), ping-pong z,
// last update writes d_out. All graph-capturable, no allocations.
// ---------------------------------------------------------------------------
extern "C" void kernel_launch(void* const* d_in, const int* in_sizes, int n_in,
                              void* d_out, int out_size) {
    const float* x  = (const float*)d_in[0];   // [B, O]
    const float* W  = (const float*)d_in[1];   // [O, L]
    const float* mu = (const float*)d_in[2];   // [L]
    // d_in[3] = inf_iters (device scalar) -- fixed at 20 by problem spec;
    // cannot be read on host under graph capture, so the 20 iterations are
    // unrolled as launches.
    float* out = (float*)d_out;

    float *Z0, *Z1, *G;
    cudaGetSymbolAddress((void**)&Z0, g_Z0);
    cudaGetSymbolAddress((void**)&Z1, g_Z1);
    cudaGetSymbolAddress((void**)&G,  g_G);

    init_z_kernel<<<(B_DIM * L_DIM / 4) / 256, 256>>>(mu, Z0);

    float* zb[2] = {Z0, Z1};
    for (int it = 0; it < N_ITERS; ++it) {
        const float* zin = zb[it & 1];
        float* zout = (it == N_ITERS - 1) ? out : zb[(it + 1) & 1];

        // GEMM1: G = epi1( zin @ W^T ), M=B, N=O, K=L
        {
            dim3 grid(O_DIM / 128, B_DIM / 128);
            gemm_fused<128, 128, 16, 8, 8, true, 1><<<grid, 256>>>(
                zin, W, x, (const float*)nullptr, G, B_DIM, O_DIM, L_DIM);
        }
        // GEMM2: zout = epi2( G @ W ), M=B, N=L, K=O  (256 CTAs -> full chip)
        {
            dim3 grid(L_DIM / 64, B_DIM / 64);
            gemm_fused<64, 64, 32, 8, 4, false, 2><<<grid, 128>>>(
                G, W, zin, mu, zout, B_DIM, L_DIM, O_DIM);
        }
    }
}

// round 5
// speedup vs baseline: 2.5612x; 2.5612x over previous
#include <cuda_runtime.h>
#include <cuda_bf16.h>
#include <cstdint>
#include <stddef.h>
#include <math.h>

#define B_DIM 1024
#define L_DIM 1024
#define O_DIM 4096
#define N_ITERS 20
#define INF_LR   0.01f
#define SPARSE_Z 1e-3f

typedef unsigned short u16;
typedef uint32_t u32;

// ---------------- scratch (no cudaMalloc allowed) ----------------
__device__ u16   g_Whi [O_DIM * L_DIM];
__device__ u16   g_Wlo [O_DIM * L_DIM];
__device__ u16   g_WThi[L_DIM * O_DIM];
__device__ u16   g_WTlo[L_DIM * O_DIM];
__device__ u16   g_Ghi [B_DIM * O_DIM];
__device__ u16   g_Glo [B_DIM * O_DIM];
__device__ float g_zf  [B_DIM * L_DIM];
__device__ u16   g_zhi [B_DIM * L_DIM];
__device__ u16   g_zlo [B_DIM * L_DIM];

// ---------------- helpers ----------------
__device__ __forceinline__ u32 smem_u32(const void* p) {
    u32 a;
    asm("{ .reg .u64 t; cvta.to.shared.u64 t, %1; cvt.u32.u64 %0, t; }" : "=r"(a) : "l"(p));
    return a;
}
__device__ __forceinline__ void cp16(u32 dst, const void* src) {
    asm volatile("cp.async.cg.shared.global [%0], [%1], 16;" :: "r"(dst), "l"(src));
}
__device__ __forceinline__ void cp_commit() { asm volatile("cp.async.commit_group;"); }
template <int N> __device__ __forceinline__ void cp_wait() {
    asm volatile("cp.async.wait_group %0;" :: "n"(N));
}
__device__ __forceinline__ void ldsm4(u32* r, u32 a) {
    asm volatile("ldmatrix.sync.aligned.m8n8.x4.shared.b16 {%0,%1,%2,%3}, [%4];"
                 : "=r"(r[0]), "=r"(r[1]), "=r"(r[2]), "=r"(r[3]) : "r"(a));
}
__device__ __forceinline__ void mma_bf16(float* d, const u32* a, u32 b0, u32 b1) {
    asm volatile(
        "mma.sync.aligned.m16n8k16.row.col.f32.bf16.bf16.f32 "
        "{%0,%1,%2,%3},{%4,%5,%6,%7},{%8,%9},{%0,%1,%2,%3};"
        : "+f"(d[0]), "+f"(d[1]), "+f"(d[2]), "+f"(d[3])
        : "r"(a[0]), "r"(a[1]), "r"(a[2]), "r"(a[3]), "r"(b0), "r"(b1));
}
__device__ __forceinline__ void split2(float v, u16& h, u16& l) {
    __nv_bfloat16 bh = __float2bfloat16(v);
    h = __bfloat16_as_ushort(bh);
    l = __bfloat16_as_ushort(__float2bfloat16(v - __bfloat162float(bh)));
}
__device__ __forceinline__ u32 swz(u32 off) { return off ^ ((off >> 3) & 0x70u); }

// ---------------- one-time prep ----------------
__global__ void prep_w(const float* __restrict__ W,
                       u16* __restrict__ Whi, u16* __restrict__ Wlo,
                       u16* __restrict__ WThi, u16* __restrict__ WTlo) {
    __shared__ float t[32][33];
    int tx = threadIdx.x, ty = threadIdx.y;
    int lx = blockIdx.x * 32, oy = blockIdx.y * 32;
#pragma unroll
    for (int r = 0; r < 32; r += 8) {
        size_t idx = (size_t)(oy + ty + r) * L_DIM + lx + tx;
        float v = W[idx];
        u16 h, l; split2(v, h, l);
        Whi[idx] = h; Wlo[idx] = l;
        t[ty + r][tx] = v;
    }
    __syncthreads();
#pragma unroll
    for (int r = 0; r < 32; r += 8) {
        float v = t[tx][ty + r];
        size_t idx = (size_t)(lx + ty + r) * O_DIM + oy + tx;
        u16 h, l; split2(v, h, l);
        WThi[idx] = h; WTlo[idx] = l;
    }
}

__global__ void init_z(const float* __restrict__ mu, float* __restrict__ zf,
                       u16* __restrict__ zhi, u16* __restrict__ zlo) {
    int i = blockIdx.x * blockDim.x + threadIdx.x;
    float v = mu[i & (L_DIM - 1)];
    zf[i] = v;
    u16 h, l; split2(v, h, l);
    zhi[i] = h; zlo[i] = l;
}

// ---------------- pipelined bf16 split-GEMM with fused epilogue -------------
// C[m,n] = sum_k A[m,k]*B[n,k]   (A [M,K] k-contig, B [N,K] k-contig)
// 3-term split: Ahi*Bhi + Ahi*Blo + Alo*Bhi, fp32 accumulate.
// EPI=1: p=tanh(C); g=(1-p^2)*(X - p); write g as bf16 hi/lo (Ohi/Olo).
// EPI=2: z=X (fp32); zn = z - lr*((z-mu) - C + sz*sign(z));
//        write zf (OF1), bf16 hi/lo, and optionally OF2 (= d_out).
template <int BM, int BN, int NSTAGE, int EPI, int KDIM>
__global__ void __launch_bounds__(256, 1)
gemm_mma(const u16* __restrict__ Ah, const u16* __restrict__ Al,
         const u16* __restrict__ Bh, const u16* __restrict__ Bl,
         const float* X, const float* __restrict__ MU,
         u16* __restrict__ Ohi, u16* __restrict__ Olo,
         float* OF1, float* OF2) {
    constexpr int BK = 64, ROWB = 128;
    constexpr int MF = BM / 32;                       // warp M = BM/2, frags of 16
    constexpr int ABYTES = BM * ROWB, BBYTES = BN * ROWB;
    constexpr int STAGE = 2 * (ABYTES + BBYTES);
    constexpr int CPA = ABYTES / 16, CPB = BBYTES / 16;
    constexpr int TOT = 2 * (CPA + CPB);
    constexpr int S = KDIM / BK;
    static_assert(TOT % 256 == 0, "loader divisibility");

    extern __shared__ char sraw[];
    const u32 smem0 = (smem_u32(sraw) + 127u) & ~127u;

    const int tid = threadIdx.x, lane = tid & 31, wid = tid >> 5;
    const int wm = wid >> 2, wn = wid & 3;           // 2 x 4 warps
    const int bm = blockIdx.y * BM, bn = blockIdx.x * BN;

    auto load_stage = [&](int s, int buf) {
        const u32 sb = smem0 + (u32)buf * STAGE;
        const int k0 = s * BK;
#pragma unroll
        for (int i = 0; i < TOT / 256; i++) {
            int c = tid + i * 256;
            const u16* src; u32 tb; int local, rowbase;
            if (c < CPA)                 { src = Ah; tb = sb;                        local = c;                 rowbase = bm; }
            else if (c < 2 * CPA)        { src = Al; tb = sb + ABYTES;               local = c - CPA;           rowbase = bm; }
            else if (c < 2 * CPA + CPB)  { src = Bh; tb = sb + 2 * ABYTES;           local = c - 2 * CPA;       rowbase = bn; }
            else                         { src = Bl; tb = sb + 2 * ABYTES + BBYTES;  local = c - 2 * CPA - CPB; rowbase = bn; }
            int row = local >> 3, c16 = local & 7;
            cp16(tb + swz((u32)(row * ROWB + c16 * 16)),
                 src + (size_t)(rowbase + row) * KDIM + k0 + c16 * 8);
        }
    };

    float acc[MF][4][4];
#pragma unroll
    for (int a = 0; a < MF; a++)
#pragma unroll
        for (int b = 0; b < 4; b++)
#pragma unroll
            for (int k = 0; k < 4; k++) acc[a][b][k] = 0.f;

    // per-thread ldmatrix address components
    const int aRow = wm * (BM / 2) + (lane & 15);
    const int bRow = wn * 32 + lane;
    const u32 aOff = (u32)aRow * ROWB, aSx = ((u32)(aRow & 7)) << 4;
    const u32 aK = ((u32)(lane >> 4)) << 4;
    const u32 bOff = (u32)bRow * ROWB, bSx = ((u32)(bRow & 7)) << 4;

#pragma unroll
    for (int p = 0; p < NSTAGE - 1; p++) { load_stage(p, p); cp_commit(); }

    int cbuf = 0, lbuf = NSTAGE - 1;
    for (int s = 0; s < S; s++) {
        cp_wait<NSTAGE - 2>();
        __syncthreads();
        if (s + NSTAGE - 1 < S) load_stage(s + NSTAGE - 1, lbuf);
        cp_commit();
        if (++lbuf == NSTAGE) lbuf = 0;

        const u32 sb = smem0 + (u32)cbuf * STAGE;
        const u32 sAh = sb, sAl = sb + ABYTES;
        const u32 sBh = sb + 2 * ABYTES, sBl = sb + 2 * ABYTES + BBYTES;
#pragma unroll
        for (int ks = 0; ks < BK / 16; ks++) {
            u32 ah[MF][4], al[MF][4];
#pragma unroll
            for (int mf = 0; mf < MF; mf++) {
                u32 ro = aOff + (u32)(mf * 16 * ROWB);
                u32 ko = (((u32)(ks * 32) + aK) ^ aSx);
                ldsm4(ah[mf], sAh + ro + ko);
                ldsm4(al[mf], sAl + ro + ko);
            }
            u32 bh0[4], bh1[4], bl0[4], bl1[4];
            {
                u32 k0o = (((u32)(ks * 32)) ^ bSx);
                u32 k1o = (((u32)(ks * 32 + 16)) ^ bSx);
                ldsm4(bh0, sBh + bOff + k0o);
                ldsm4(bh1, sBh + bOff + k1o);
                ldsm4(bl0, sBl + bOff + k0o);
                ldsm4(bl1, sBl + bOff + k1o);
            }
#pragma unroll
            for (int mf = 0; mf < MF; mf++)
#pragma unroll
                for (int nf = 0; nf < 4; nf++) {
                    mma_bf16(acc[mf][nf], ah[mf], bh0[nf], bh1[nf]);
                    mma_bf16(acc[mf][nf], ah[mf], bl0[nf], bl1[nf]);
                    mma_bf16(acc[mf][nf], al[mf], bh0[nf], bh1[nf]);
                }
        }
        if (++cbuf == NSTAGE) cbuf = 0;
    }

    // ---- fused epilogue ----
    constexpr int OST = (EPI == 1) ? O_DIM : L_DIM;
#pragma unroll
    for (int mf = 0; mf < MF; mf++) {
#pragma unroll
        for (int nf = 0; nf < 4; nf++) {
            int r0 = bm + wm * (BM / 2) + mf * 16 + (lane >> 2);
            int cc = bn + wn * 32 + nf * 8 + (lane & 3) * 2;
#pragma unroll
            for (int h = 0; h < 2; h++) {
                int r = r0 + h * 8;
                float d0 = acc[mf][nf][2 * h], d1 = acc[mf][nf][2 * h + 1];
                size_t off = (size_t)r * OST + cc;
                if (EPI == 1) {
                    float2 xv = *(const float2*)(X + off);
                    float p0 = tanhf(d0), p1 = tanhf(d1);
                    float g0 = (1.f - p0 * p0) * (xv.x - p0);
                    float g1 = (1.f - p1 * p1) * (xv.y - p1);
                    u16 h0, l0, h1, l1;
                    split2(g0, h0, l0); split2(g1, h1, l1);
                    *(u32*)(Ohi + off) = (u32)h0 | ((u32)h1 << 16);
                    *(u32*)(Olo + off) = (u32)l0 | ((u32)l1 << 16);
                } else {
                    float2 zv = *(const float2*)(X + off);
                    float2 mv = *(const float2*)(MU + cc);
                    float s0 = (float)((zv.x > 0.f) - (zv.x < 0.f));
                    float s1 = (float)((zv.y > 0.f) - (zv.y < 0.f));
                    float zn0 = zv.x - INF_LR * ((zv.x - mv.x) - d0 + SPARSE_Z * s0);
                    float zn1 = zv.y - INF_LR * ((zv.y - mv.y) - d1 + SPARSE_Z * s1);
                    *(float2*)(OF1 + off) = make_float2(zn0, zn1);
                    u16 h0, l0, h1, l1;
                    split2(zn0, h0, l0); split2(zn1, h1, l1);
                    *(u32*)(Ohi + off) = (u32)h0 | ((u32)h1 << 16);
                    *(u32*)(Olo + off) = (u32)l0 | ((u32)l1 << 16);
                    if (OF2) *(float2*)(OF2 + off) = make_float2(zn0, zn1);
                }
            }
        }
    }
}

// ---------------- launch ----------------
extern "C" void kernel_launch(void* const* d_in, const int* in_sizes, int n_in,
                              void* d_out, int out_size) {
    const float* x  = (const float*)d_in[0];   // [B, O]
    const float* W  = (const float*)d_in[1];   // [O, L]
    const float* mu = (const float*)d_in[2];   // [L]
    // d_in[3] = inf_iters (device scalar; fixed at 20 by the problem spec,
    // unreadable on host under graph capture -> iterations unrolled as launches)
    float* out = (float*)d_out;                // [B, L]

    u16 *Whi, *Wlo, *WThi, *WTlo, *Ghi, *Glo, *zhi, *zlo;
    float* zf;
    cudaGetSymbolAddress((void**)&Whi,  g_Whi);
    cudaGetSymbolAddress((void**)&Wlo,  g_Wlo);
    cudaGetSymbolAddress((void**)&WThi, g_WThi);
    cudaGetSymbolAddress((void**)&WTlo, g_WTlo);
    cudaGetSymbolAddress((void**)&Ghi,  g_Ghi);
    cudaGetSymbolAddress((void**)&Glo,  g_Glo);
    cudaGetSymbolAddress((void**)&zf,   g_zf);
    cudaGetSymbolAddress((void**)&zhi,  g_zhi);
    cudaGetSymbolAddress((void**)&zlo,  g_zlo);

    constexpr int SM1 = 3 * 2 * (128 * 128 + 128 * 128);  // 196608
    constexpr int SM2 = 4 * 2 * (64 * 128 + 128 * 128);   // 196608

    cudaFuncSetAttribute(gemm_mma<128, 128, 3, 1, L_DIM>,
                         cudaFuncAttributeMaxDynamicSharedMemorySize, SM1 + 256);
    cudaFuncSetAttribute(gemm_mma<64, 128, 4, 2, O_DIM>,
                         cudaFuncAttributeMaxDynamicSharedMemorySize, SM2 + 256);

    prep_w<<<dim3(L_DIM / 32, O_DIM / 32), dim3(32, 8)>>>(W, Whi, Wlo, WThi, WTlo);
    init_z<<<(B_DIM * L_DIM) / 256, 256>>>(mu, zf, zhi, zlo);

    for (int it = 0; it < N_ITERS; ++it) {
        // GEMM1: C[b,o] = z @ W^T; fused tanh-deriv epilogue -> G (bf16 hi/lo)
        gemm_mma<128, 128, 3, 1, L_DIM>
            <<<dim3(O_DIM / 128, B_DIM / 128), 256, SM1 + 256>>>(
                zhi, zlo, Whi, Wlo, x, nullptr, Ghi, Glo, nullptr, nullptr);

        // GEMM2: C[b,l] = G @ W (B = WT[l,o]); fused z-update (in-place zf)
        gemm_mma<64, 128, 4, 2, O_DIM>
            <<<dim3(L_DIM / 128, B_DIM / 64), 256, SM2 + 256>>>(
                Ghi, Glo, WThi, WTlo, zf, mu, zhi, zlo, zf,
                (it == N_ITERS - 1) ? out : nullptr);
    }
}